// round 1
// baseline (speedup 1.0000x reference)
#include <cuda_runtime.h>
#include <math.h>

#define Bsz 32
#define Ssz 2048
#define Hsz 1024
#define ECH 4                   // e-chunks for u partial sums
#define WPC 8                   // warps per CTA in pass1
#define CPB 8                   // CTAs per batch element in pass1
#define SPLITS (WPC*CPB)        // 64 warp-splits per batch row
#define RPW (Ssz/SPLITS)        // 32 rows per warp

// Scratch (device globals: allocation-free per harness rules)
__device__ float  g_u_part[ECH][Hsz];
__device__ float  g_scores[Bsz*Ssz];
__device__ float  g_part_m[Bsz*SPLITS];
__device__ float  g_part_l[Bsz*SPLITS];
__device__ float4 g_part_acc[Bsz*SPLITS*(Hsz/4)];

// K0: u[h] = sum_e v[e] * W[e, H+h], split over ECH e-chunks for parallelism.
__global__ void k_u(const float* __restrict__ W, const float* __restrict__ v) {
    int h  = blockIdx.x * blockDim.x + threadIdx.x;   // 0..1023
    int e0 = blockIdx.y * (Hsz/ECH);
    float s = 0.f;
    #pragma unroll 8
    for (int e = e0; e < e0 + Hsz/ECH; ++e)
        s = fmaf(__ldg(v + e), __ldg(W + (size_t)e*(2*Hsz) + Hsz + h), s);
    g_u_part[blockIdx.y][h] = s;
}

// K1: single pass over encoder_outputs. Each warp owns 32 sequence rows of one
// batch element, computes score = enc_row . u, maintains online-softmax
// (m, l, acc[32 regs/lane]) so enc is read exactly once.
__global__ void __launch_bounds__(256, 2) k_pass1(const float* __restrict__ enc) {
    __shared__ float4 su[Hsz/4];
    // Build u in smem (sum the ECH partials)
    for (int i = threadIdx.x; i < Hsz/4; i += blockDim.x) {
        float4 a = ((const float4*)g_u_part[0])[i];
        #pragma unroll
        for (int c = 1; c < ECH; ++c) {
            float4 p = ((const float4*)g_u_part[c])[i];
            a.x += p.x; a.y += p.y; a.z += p.z; a.w += p.w;
        }
        su[i] = a;
    }
    __syncthreads();

    int b    = blockIdx.x / CPB;
    int warp = (blockIdx.x % CPB) * WPC + (threadIdx.x >> 5);
    int lane = threadIdx.x & 31;
    int s0   = warp * RPW;

    const float4* base = (const float4*)enc + (size_t)(b*Ssz + s0) * (Hsz/4);

    float acc[32];
    #pragma unroll
    for (int i = 0; i < 32; ++i) acc[i] = 0.f;
    float m = -INFINITY, l = 0.f;

    for (int r = 0; r < RPW; ++r) {
        const float4* row = base + (size_t)r * (Hsz/4);
        float4 x[8];
        #pragma unroll
        for (int j = 0; j < 8; ++j) x[j] = row[j*32 + lane];

        float dot = 0.f;
        #pragma unroll
        for (int j = 0; j < 8; ++j) {
            float4 uv = su[j*32 + lane];
            dot = fmaf(x[j].x, uv.x, dot);
            dot = fmaf(x[j].y, uv.y, dot);
            dot = fmaf(x[j].z, uv.z, dot);
            dot = fmaf(x[j].w, uv.w, dot);
        }
        #pragma unroll
        for (int off = 16; off > 0; off >>= 1)
            dot += __shfl_xor_sync(0xffffffffu, dot, off);

        if (lane == 0) g_scores[b*Ssz + s0 + r] = dot;

        if (dot > m) {
            // new max: rescale (first iter: m=-inf -> alpha=0, acc := x)
            float alpha = __expf(m - dot);
            l = fmaf(l, alpha, 1.f);
            #pragma unroll
            for (int j = 0; j < 8; ++j) {
                acc[4*j+0] = fmaf(acc[4*j+0], alpha, x[j].x);
                acc[4*j+1] = fmaf(acc[4*j+1], alpha, x[j].y);
                acc[4*j+2] = fmaf(acc[4*j+2], alpha, x[j].z);
                acc[4*j+3] = fmaf(acc[4*j+3], alpha, x[j].w);
            }
            m = dot;
        } else {
            float p = __expf(dot - m);
            l += p;
            #pragma unroll
            for (int j = 0; j < 8; ++j) {
                acc[4*j+0] = fmaf(p, x[j].x, acc[4*j+0]);
                acc[4*j+1] = fmaf(p, x[j].y, acc[4*j+1]);
                acc[4*j+2] = fmaf(p, x[j].z, acc[4*j+2]);
                acc[4*j+3] = fmaf(p, x[j].w, acc[4*j+3]);
            }
        }
    }

    int pidx = b*SPLITS + warp;
    if (lane == 0) { g_part_m[pidx] = m; g_part_l[pidx] = l; }
    #pragma unroll
    for (int j = 0; j < 8; ++j)
        g_part_acc[(size_t)pidx*(Hsz/4) + j*32 + lane] =
            make_float4(acc[4*j], acc[4*j+1], acc[4*j+2], acc[4*j+3]);
}

// K2: per batch element, merge 64 partials -> context (out[0:B*H]) and
// attention weights (out[B*H : B*H + B*S]).
__global__ void k_combine(float* __restrict__ out) {
    int b = blockIdx.x;
    int t = threadIdx.x;  // 256 threads; t indexes one float4 of H

    float M = -INFINITY;
    #pragma unroll
    for (int k = 0; k < SPLITS; ++k)
        M = fmaxf(M, g_part_m[b*SPLITS + k]);

    float L = 0.f;
    float4 c = make_float4(0.f, 0.f, 0.f, 0.f);
    for (int k = 0; k < SPLITS; ++k) {
        float wk = __expf(g_part_m[b*SPLITS + k] - M);
        L = fmaf(wk, g_part_l[b*SPLITS + k], L);
        float4 a = g_part_acc[(size_t)(b*SPLITS + k)*(Hsz/4) + t];
        c.x = fmaf(wk, a.x, c.x);
        c.y = fmaf(wk, a.y, c.y);
        c.z = fmaf(wk, a.z, c.z);
        c.w = fmaf(wk, a.w, c.w);
    }
    float inv = 1.f / L;
    c.x *= inv; c.y *= inv; c.z *= inv; c.w *= inv;
    ((float4*)out)[b*(Hsz/4) + t] = c;

    // attention weights: softmax(scores) with the exact same M, L
    float* wout = out + Bsz*Hsz + b*Ssz;
    for (int s = t; s < Ssz; s += blockDim.x)
        wout[s] = __expf(g_scores[b*Ssz + s] - M) * inv;
}

extern "C" void kernel_launch(void* const* d_in, const int* in_sizes, int n_in,
                              void* d_out, int out_size) {
    // metadata order: hidden_state, encoder_outputs, W, b, v, batch_size, seq_len
    const float* enc = (const float*)d_in[1];
    const float* W   = (const float*)d_in[2];
    const float* v   = (const float*)d_in[4];
    float* out = (float*)d_out;

    k_u<<<dim3(Hsz/128, ECH), 128>>>(W, v);
    k_pass1<<<Bsz*CPB, 256>>>(enc);
    k_combine<<<Bsz, 256>>>(out);
}